// round 1
// baseline (speedup 1.0000x reference)
#include <cuda_runtime.h>

// Problem shape (fixed by the dataset): x (B,L,C,H,W) = (2,24,32,128,256) fp32,
// params_log_base (2,C,R) = (2,32,32) fp32. Output y same shape as x.
// Math: exact causal FIR conv along L (the reference's rfft(48) path has no
// circular aliasing since 2L-1=47 <= 48).

#define B_ 2
#define L_ 24
#define C_ 32
#define H_ 128
#define W_ 256
#define R_ 32

// Scratch for the per-channel impulse response k[c][t] (no cudaMalloc allowed).
__device__ float g_k[C_ * L_];

// ---------------------------------------------------------------------------
// Kernel 1: compute k[c,t] = sum_r gamma * exp(-t*nu) * cos(t*theta)
// 768 threads total; cost is negligible.
// ---------------------------------------------------------------------------
__global__ void ConvLRU_k_kernel(const float* __restrict__ p) {
    int idx = blockIdx.x * blockDim.x + threadIdx.x;
    if (idx >= C_ * L_) return;
    int c = idx / L_;
    int t = idx % L_;
    float tf = (float)t;
    float acc = 0.0f;
#pragma unroll
    for (int r = 0; r < R_; r++) {
        float nu_log    = p[c * R_ + r];              // params[0,c,r]
        float theta_log = p[C_ * R_ + c * R_ + r];    // params[1,c,r]
        float nu    = expf(nu_log);
        float theta = expf(theta_log);
        float lam2  = expf(-2.0f * nu);               // |lambda|^2
        float gamma = sqrtf(fmaxf(1.0f - lam2, 1e-12f));
        acc += gamma * expf(-tf * nu) * cosf(tf * theta);
    }
    g_k[idx] = acc;
}

// ---------------------------------------------------------------------------
// Kernel 2: causal conv along L. One thread per (b,c,h,w/4) float4 pixel.
// Loads all 24 sequence samples (independent LDG.128 -> deep MLP), fully
// unrolled triangular MAC, 24 STG.128. Memory-bound by design.
// ---------------------------------------------------------------------------
__global__ __launch_bounds__(256)
void ConvLRU_conv_kernel(const float4* __restrict__ x, float4* __restrict__ y) {
    constexpr int W4   = W_ / 4;        // 64
    constexpr int HW4  = H_ * W4;       // 8192 (divisible by 256 -> c uniform per block)
    constexpr int strideL = C_ * HW4;   // float4 stride between consecutive l

    int gid = blockIdx.x * 256 + threadIdx.x;   // over B*C*HW4 = 524288
    int hw  = gid % HW4;
    int bc  = gid / HW4;
    int c   = bc % C_;
    int b   = bc / C_;

    __shared__ float sk[L_];
    if (threadIdx.x < L_) sk[threadIdx.x] = g_k[c * L_ + threadIdx.x];
    __syncthreads();

    int base = (b * (L_ * C_) + c) * HW4 + hw;  // float4 index of l=0 sample

    float4 xv[L_];
#pragma unroll
    for (int l = 0; l < L_; l++) {
        xv[l] = x[base + l * strideL];
    }

#pragma unroll
    for (int l = 0; l < L_; l++) {
        float4 acc = make_float4(0.f, 0.f, 0.f, 0.f);
#pragma unroll
        for (int t = 0; t <= l; t++) {
            float kv = sk[t];
            float4 xs = xv[l - t];
            acc.x = fmaf(kv, xs.x, acc.x);
            acc.y = fmaf(kv, xs.y, acc.y);
            acc.z = fmaf(kv, xs.z, acc.z);
            acc.w = fmaf(kv, xs.w, acc.w);
        }
        y[base + l * strideL] = acc;
    }
}

// ---------------------------------------------------------------------------
extern "C" void kernel_launch(void* const* d_in, const int* in_sizes, int n_in,
                              void* d_out, int out_size) {
    const float* x = (const float*)d_in[0];        // (B,L,C,H,W)
    const float* p = (const float*)d_in[1];        // (2,C,R)
    float* y = (float*)d_out;

    ConvLRU_k_kernel<<<(C_ * L_ + 255) / 256, 256>>>(p);

    constexpr int total4 = B_ * C_ * H_ * (W_ / 4);  // 524288
    ConvLRU_conv_kernel<<<total4 / 256, 256>>>((const float4*)x, (float4*)y);
}

// round 2
// speedup vs baseline: 1.0959x; 1.0959x over previous
#include <cuda_runtime.h>

// x (B,L,C,H,W) = (2,24,32,128,256) fp32, params (2,C,R) = (2,32,32) fp32.
// Exact causal FIR conv along L (reference's rfft(48) has no aliasing, 2L-1=47<=48).
// Single fused kernel: per-block k[c][*] computation (warp-parallel over rank r,
// warp w + chunk j -> tap t = 8j+w) followed by the memory-bound triangular MAC.

#define B_ 2
#define L_ 24
#define C_ 32
#define H_ 128
#define W_ 256
#define R_ 32

__global__ __launch_bounds__(256, 2)
void ConvLRU_fused_kernel(const float4* __restrict__ x,
                          const float*  __restrict__ p,
                          float4* __restrict__ y) {
    constexpr int W4      = W_ / 4;       // 64
    constexpr int HW4     = H_ * W4;      // 8192 (divisible by 256 -> c uniform per block)
    constexpr int strideL = C_ * HW4;     // float4 stride between consecutive l

    int gid = blockIdx.x * 256 + threadIdx.x;   // over B*C*HW4 = 524288
    int hw  = gid % HW4;
    int bc  = gid / HW4;
    int c   = bc % C_;
    int b   = bc / C_;

    __shared__ float sk[L_];

    // ---- k[c][t] = sum_r gamma * exp(-t*nu) * cos(t*theta), warp-parallel ----
    {
        int lane = threadIdx.x & 31;       // = r
        int w    = threadIdx.x >> 5;       // warp id 0..7
        float nu_log    = p[c * R_ + lane];
        float theta_log = p[C_ * R_ + c * R_ + lane];
        float nu    = __expf(nu_log);
        float theta = __expf(theta_log);
        float lam2  = __expf(-2.0f * nu);
        float gamma = sqrtf(fmaxf(1.0f - lam2, 1e-12f));
#pragma unroll
        for (int j = 0; j < 3; j++) {
            int   t  = 8 * j + w;          // 0..23 exactly once per warp/chunk
            float tf = (float)t;
            float term = gamma * __expf(-tf * nu) * __cosf(tf * theta);
            // warp reduction over r
#pragma unroll
            for (int off = 16; off > 0; off >>= 1)
                term += __shfl_xor_sync(0xFFFFFFFFu, term, off);
            if (lane == 0) sk[t] = term;
        }
    }

    // ---- issue all 24 sequence loads (independent; deep MLP, evict-first) ----
    int base = (b * (L_ * C_) + c) * HW4 + hw;  // float4 index of l=0 sample

    float4 xv[L_];
#pragma unroll
    for (int l = 0; l < L_; l++) {
        xv[l] = __ldcs(&x[base + l * strideL]);
    }

    __syncthreads();   // sk visible; xv loads still in flight

    // ---- triangular causal MAC + streaming stores ----
#pragma unroll
    for (int l = 0; l < L_; l++) {
        float4 acc = make_float4(0.f, 0.f, 0.f, 0.f);
#pragma unroll
        for (int t = 0; t <= l; t++) {
            float  kv = sk[t];
            float4 xs = xv[l - t];
            acc.x = fmaf(kv, xs.x, acc.x);
            acc.y = fmaf(kv, xs.y, acc.y);
            acc.z = fmaf(kv, xs.z, acc.z);
            acc.w = fmaf(kv, xs.w, acc.w);
        }
        __stcs(&y[base + l * strideL], acc);
    }
}

extern "C" void kernel_launch(void* const* d_in, const int* in_sizes, int n_in,
                              void* d_out, int out_size) {
    const float* x = (const float*)d_in[0];        // (B,L,C,H,W)
    const float* p = (const float*)d_in[1];        // (2,C,R)
    float* y = (float*)d_out;

    constexpr int total4 = B_ * C_ * H_ * (W_ / 4);  // 524288
    ConvLRU_fused_kernel<<<total4 / 256, 256>>>((const float4*)x, p, (float4*)y);
}